// round 7
// baseline (speedup 1.0000x reference)
#include <cuda_runtime.h>

#define N_NODES 100000
#define DD 64
#define E_EDGES 1600000

// Scratch (static device globals — no allocation allowed)
__device__ float g_agg[N_NODES * DD];
__device__ float g_h1[N_NODES * DD];
__device__ int   g_is64;   // 1 if edge_index is int64, 0 if int32

// ---------------------------------------------------------------------------
// Detect edge_index dtype. If the buffer is int64 (little-endian, values in
// [0, 2^31)), every odd int32 word is 0. If int32, odd words are random node
// ids — OR over 4096 of them is ~surely nonzero.
// ---------------------------------------------------------------------------
__global__ void detect_dtype_kernel(const int* __restrict__ ei32) {
    __shared__ int s_or;
    if (threadIdx.x == 0) s_or = 0;
    __syncthreads();
    int v = 0;
    for (int i = threadIdx.x; i < 4096; i += 256)
        v |= ei32[2 * i + 1];
    atomicOr(&s_or, v);
    __syncthreads();
    if (threadIdx.x == 0) g_is64 = (s_or == 0) ? 1 : 0;
}

// ---------------------------------------------------------------------------
// Zero the aggregation buffer (float4 grid-stride)
// ---------------------------------------------------------------------------
__global__ void zero_agg_kernel() {
    int n4 = N_NODES * DD / 4;
    float4 z = make_float4(0.f, 0.f, 0.f, 0.f);
    float4* p = reinterpret_cast<float4*>(g_agg);
    for (int i = blockIdx.x * blockDim.x + threadIdx.x; i < n4;
         i += gridDim.x * blockDim.x)
        p[i] = z;
}

// ---------------------------------------------------------------------------
// Edge scatter: agg[dst] += h[src].
// One thread per (edge, 16-byte chunk): 16 threads/edge.
// float4 source load, 4 scalar atomicAdd (REDG.E.ADD.F32) stores.
// ---------------------------------------------------------------------------
__global__ void __launch_bounds__(256) scatter_kernel(
        const float* __restrict__ xin,
        const void* __restrict__ ei_raw,
        int use_h1) {
    int t = blockIdx.x * blockDim.x + threadIdx.x;
    int e = t >> 4;
    if (e >= E_EDGES) return;
    int c = (t & 15) << 2;

    int src, dst;
    if (g_is64) {
        const long long* ei = (const long long*)ei_raw;
        src = (int)ei[e];
        dst = (int)ei[E_EDGES + e];
    } else {
        const int* ei = (const int*)ei_raw;
        src = ei[e];
        dst = ei[E_EDGES + e];
    }

    const float* h = use_h1 ? g_h1 : xin;
    float4 v = *reinterpret_cast<const float4*>(h + src * DD + c);
    float* addr = g_agg + dst * DD + c;
    atomicAdd(addr + 0, v.x);
    atomicAdd(addr + 1, v.y);
    atomicAdd(addr + 2, v.z);
    atomicAdd(addr + 3, v.w);
}

// ---------------------------------------------------------------------------
// Layer 1: g_h1 = relu((g_agg + (1+eps0)*x) @ W0^T)
// blockDim (64,4); 8 nodes per tile (each thread does rows ty and ty+4).
// W stored transposed+padded in smem: Wt[k][j] at Wt[k*65+j] -> conflict-free.
// ---------------------------------------------------------------------------
__global__ void __launch_bounds__(256) gin1_kernel(
        const float* __restrict__ x,
        const float* __restrict__ W0,
        const float* __restrict__ eps0p) {
    __shared__ float Wt[64 * 65];
    __shared__ float hs[8][64];

    int tx = threadIdx.x, ty = threadIdx.y;
    int tid = ty * 64 + tx;

    for (int i = tid; i < 4096; i += 256) {
        int j = i >> 6, k = i & 63;      // W0[j][k], torch layout [out,in]
        Wt[k * 65 + j] = W0[i];
    }
    float se = 1.0f + *eps0p;
    __syncthreads();

    int ntiles = N_NODES / 8;  // 12500
    for (int tile = blockIdx.x; tile < ntiles; tile += gridDim.x) {
        int base = tile * 8;
        #pragma unroll
        for (int r = 0; r < 2; r++) {
            int row = ty + r * 4;
            int node = base + row;
            hs[row][tx] = g_agg[node * DD + tx] + se * x[node * DD + tx];
        }
        __syncthreads();

        float acc0 = 0.f, acc1 = 0.f;
        #pragma unroll
        for (int k = 0; k < 64; k++) {
            float w = Wt[k * 65 + tx];
            acc0 = fmaf(hs[ty][k], w, acc0);
            acc1 = fmaf(hs[ty + 4][k], w, acc1);
        }
        g_h1[(base + ty) * DD + tx]     = fmaxf(acc0, 0.f);
        g_h1[(base + ty + 4) * DD + tx] = fmaxf(acc1, 0.f);
        __syncthreads();
    }
}

// ---------------------------------------------------------------------------
// Final: out = ( g_h1 @ Wm^T + relu((g_agg + (1+eps1)*g_h1) @ W1^T) ) / 2
// Same tiling; two weight matrices resident in smem.
// ---------------------------------------------------------------------------
__global__ void __launch_bounds__(256) final_kernel(
        const float* __restrict__ W1,
        const float* __restrict__ eps1p,
        const float* __restrict__ Wm,
        float* __restrict__ out) {
    __shared__ float Wt1[64 * 65];
    __shared__ float Wtm[64 * 65];
    __shared__ float us[8][64];
    __shared__ float hh[8][64];

    int tx = threadIdx.x, ty = threadIdx.y;
    int tid = ty * 64 + tx;

    for (int i = tid; i < 4096; i += 256) {
        int j = i >> 6, k = i & 63;
        Wt1[k * 65 + j] = W1[i];
        Wtm[k * 65 + j] = Wm[i];
    }
    float se = 1.0f + *eps1p;
    __syncthreads();

    int ntiles = N_NODES / 8;
    for (int tile = blockIdx.x; tile < ntiles; tile += gridDim.x) {
        int base = tile * 8;
        #pragma unroll
        for (int r = 0; r < 2; r++) {
            int row = ty + r * 4;
            int node = base + row;
            float h = g_h1[node * DD + tx];
            us[row][tx] = g_agg[node * DD + tx] + se * h;
            hh[row][tx] = h;
        }
        __syncthreads();

        float a0 = 0.f, a1 = 0.f, b0 = 0.f, b1 = 0.f;
        #pragma unroll
        for (int k = 0; k < 64; k++) {
            float w1 = Wt1[k * 65 + tx];
            float wm = Wtm[k * 65 + tx];
            float u0 = us[ty][k],     u1 = us[ty + 4][k];
            float q0 = hh[ty][k],     q1 = hh[ty + 4][k];
            a0 = fmaf(u0, w1, a0);
            a1 = fmaf(u1, w1, a1);
            b0 = fmaf(q0, wm, b0);
            b1 = fmaf(q1, wm, b1);
        }
        out[(base + ty) * DD + tx]     = 0.5f * (b0 + fmaxf(a0, 0.f));
        out[(base + ty + 4) * DD + tx] = 0.5f * (b1 + fmaxf(a1, 0.f));
        __syncthreads();
    }
}

// ---------------------------------------------------------------------------
// Launch
// ---------------------------------------------------------------------------
extern "C" void kernel_launch(void* const* d_in, const int* in_sizes, int n_in,
                              void* d_out, int out_size) {
    const float* x    = (const float*)d_in[0];
    const void*  ei   = d_in[1];
    const float* W0   = (const float*)d_in[2];
    const float* eps0 = (const float*)d_in[3];
    const float* W1   = (const float*)d_in[4];
    const float* eps1 = (const float*)d_in[5];
    const float* Wm   = (const float*)d_in[6];
    float*       out  = (float*)d_out;

    dim3 gemm_block(64, 4);
    int scatter_blocks = (E_EDGES * 16) / 256;  // 100000 exactly

    detect_dtype_kernel<<<1, 256>>>((const int*)ei);

    // Layer 1
    zero_agg_kernel<<<1184, 256>>>();
    scatter_kernel<<<scatter_blocks, 256>>>(x, ei, 0);
    gin1_kernel<<<592, gemm_block>>>(x, W0, eps0);

    // Layer 2 + final mix
    zero_agg_kernel<<<1184, 256>>>();
    scatter_kernel<<<scatter_blocks, 256>>>(x, ei, 1);
    final_kernel<<<592, gemm_block>>>(W1, eps1, Wm, out);
}

// round 9
// speedup vs baseline: 1.6423x; 1.6423x over previous
#include <cuda_runtime.h>

#define N_NODES 100000
#define DD 64
#define E_EDGES 1600000

// Scratch (static device globals — no allocation allowed)
__device__ float g_agg[N_NODES * DD];
__device__ float g_h1[N_NODES * DD];
__device__ int   g_is64;   // 1 if edge_index is int64, 0 if int32

// ---------------------------------------------------------------------------
// Detect edge_index dtype. int64 (values < 2^31) -> all odd int32 words zero.
// ---------------------------------------------------------------------------
__global__ void detect_dtype_kernel(const int* __restrict__ ei32) {
    __shared__ int s_or;
    if (threadIdx.x == 0) s_or = 0;
    __syncthreads();
    int v = 0;
    for (int i = threadIdx.x; i < 4096; i += 256)
        v |= ei32[2 * i + 1];
    atomicOr(&s_or, v);
    __syncthreads();
    if (threadIdx.x == 0) g_is64 = (s_or == 0) ? 1 : 0;
}

// ---------------------------------------------------------------------------
// Zero the aggregation buffer (float4 grid-stride)
// ---------------------------------------------------------------------------
__global__ void zero_agg_kernel() {
    int n4 = N_NODES * DD / 4;
    float4 z = make_float4(0.f, 0.f, 0.f, 0.f);
    float4* p = reinterpret_cast<float4*>(g_agg);
    for (int i = blockIdx.x * blockDim.x + threadIdx.x; i < n4;
         i += gridDim.x * blockDim.x)
        p[i] = z;
}

// ---------------------------------------------------------------------------
// Edge scatter: agg[dst] += h[src].
// 16 threads/edge, float4 load + one red.global.add.v4.f32 per thread.
// (Vector red is safe — earlier traps were caused by the int64 misread.)
// ---------------------------------------------------------------------------
__global__ void __launch_bounds__(256) scatter_kernel(
        const float* __restrict__ xin,
        const void* __restrict__ ei_raw,
        int use_h1) {
    int t = blockIdx.x * blockDim.x + threadIdx.x;
    int e = t >> 4;
    if (e >= E_EDGES) return;
    int c = (t & 15) << 2;

    int src, dst;
    if (g_is64) {
        const long long* ei = (const long long*)ei_raw;
        src = (int)ei[e];
        dst = (int)ei[E_EDGES + e];
    } else {
        const int* ei = (const int*)ei_raw;
        src = ei[e];
        dst = ei[E_EDGES + e];
    }

    const float* h = use_h1 ? g_h1 : xin;
    float4 v = *reinterpret_cast<const float4*>(h + src * DD + c);
    float* addr = g_agg + dst * DD + c;
    asm volatile("red.global.add.v4.f32 [%0], {%1, %2, %3, %4};"
                 :: "l"(addr), "f"(v.x), "f"(v.y), "f"(v.z), "f"(v.w)
                 : "memory");
}

// ---------------------------------------------------------------------------
// Layer 1: g_h1 = relu((g_agg + (1+eps0)*x) @ W0^T)
// blockDim (64,4), 8 nodes/tile. W row-major in smem, stride 68 floats
// (16B-phase conflict-free for LDS.128). Inner loop: float4 weight loads +
// float4 activation broadcasts -> 3 LDS.128 per 8 FMA.
// ---------------------------------------------------------------------------
__global__ void __launch_bounds__(256) gin1_kernel(
        const float* __restrict__ x,
        const float* __restrict__ W0,
        const float* __restrict__ eps0p) {
    __shared__ float Ws[64 * 68];
    __shared__ float hs[8][64];

    int tx = threadIdx.x, ty = threadIdx.y;
    int tid = ty * 64 + tx;

    for (int i = tid; i < 4096; i += 256) {
        int j = i >> 6, k = i & 63;      // W0[j][k], torch layout [out,in]
        Ws[j * 68 + k] = W0[i];
    }
    float se = 1.0f + *eps0p;
    __syncthreads();

    const float4* w4 = reinterpret_cast<const float4*>(&Ws[tx * 68]);

    int ntiles = N_NODES / 8;  // 12500
    for (int tile = blockIdx.x; tile < ntiles; tile += gridDim.x) {
        int base = tile * 8;
        #pragma unroll
        for (int r = 0; r < 2; r++) {
            int row = ty + r * 4;
            int node = base + row;
            hs[row][tx] = g_agg[node * DD + tx] + se * x[node * DD + tx];
        }
        __syncthreads();

        const float4* h0 = reinterpret_cast<const float4*>(&hs[ty][0]);
        const float4* h1 = reinterpret_cast<const float4*>(&hs[ty + 4][0]);
        float acc0 = 0.f, acc1 = 0.f;
        #pragma unroll
        for (int kk = 0; kk < 16; kk++) {
            float4 w = w4[kk];
            float4 a = h0[kk];
            float4 b = h1[kk];
            acc0 = fmaf(a.x, w.x, acc0); acc1 = fmaf(b.x, w.x, acc1);
            acc0 = fmaf(a.y, w.y, acc0); acc1 = fmaf(b.y, w.y, acc1);
            acc0 = fmaf(a.z, w.z, acc0); acc1 = fmaf(b.z, w.z, acc1);
            acc0 = fmaf(a.w, w.w, acc0); acc1 = fmaf(b.w, w.w, acc1);
        }
        g_h1[(base + ty) * DD + tx]     = fmaxf(acc0, 0.f);
        g_h1[(base + ty + 4) * DD + tx] = fmaxf(acc1, 0.f);
        __syncthreads();
    }
}

// ---------------------------------------------------------------------------
// Final: out = ( g_h1 @ Wm^T + relu((g_agg + (1+eps1)*g_h1) @ W1^T) ) / 2
// Same vectorized scheme, two weight matrices.
// ---------------------------------------------------------------------------
__global__ void __launch_bounds__(256) final_kernel(
        const float* __restrict__ W1,
        const float* __restrict__ eps1p,
        const float* __restrict__ Wm,
        float* __restrict__ out) {
    __shared__ float Ws1[64 * 68];
    __shared__ float Wsm[64 * 68];
    __shared__ float us[8][64];
    __shared__ float hh[8][64];

    int tx = threadIdx.x, ty = threadIdx.y;
    int tid = ty * 64 + tx;

    for (int i = tid; i < 4096; i += 256) {
        int j = i >> 6, k = i & 63;
        Ws1[j * 68 + k] = W1[i];
        Wsm[j * 68 + k] = Wm[i];
    }
    float se = 1.0f + *eps1p;
    __syncthreads();

    const float4* w1v = reinterpret_cast<const float4*>(&Ws1[tx * 68]);
    const float4* wmv = reinterpret_cast<const float4*>(&Wsm[tx * 68]);

    int ntiles = N_NODES / 8;
    for (int tile = blockIdx.x; tile < ntiles; tile += gridDim.x) {
        int base = tile * 8;
        #pragma unroll
        for (int r = 0; r < 2; r++) {
            int row = ty + r * 4;
            int node = base + row;
            float h = g_h1[node * DD + tx];
            us[row][tx] = g_agg[node * DD + tx] + se * h;
            hh[row][tx] = h;
        }
        __syncthreads();

        const float4* u0 = reinterpret_cast<const float4*>(&us[ty][0]);
        const float4* u1 = reinterpret_cast<const float4*>(&us[ty + 4][0]);
        const float4* q0 = reinterpret_cast<const float4*>(&hh[ty][0]);
        const float4* q1 = reinterpret_cast<const float4*>(&hh[ty + 4][0]);

        float a0 = 0.f, a1 = 0.f, b0 = 0.f, b1 = 0.f;
        #pragma unroll
        for (int kk = 0; kk < 16; kk++) {
            float4 w1r = w1v[kk];
            float4 wmr = wmv[kk];
            float4 ua = u0[kk], ub = u1[kk];
            float4 qa = q0[kk], qb = q1[kk];
            a0 = fmaf(ua.x, w1r.x, a0); a1 = fmaf(ub.x, w1r.x, a1);
            b0 = fmaf(qa.x, wmr.x, b0); b1 = fmaf(qb.x, wmr.x, b1);
            a0 = fmaf(ua.y, w1r.y, a0); a1 = fmaf(ub.y, w1r.y, a1);
            b0 = fmaf(qa.y, wmr.y, b0); b1 = fmaf(qb.y, wmr.y, b1);
            a0 = fmaf(ua.z, w1r.z, a0); a1 = fmaf(ub.z, w1r.z, a1);
            b0 = fmaf(qa.z, wmr.z, b0); b1 = fmaf(qb.z, wmr.z, b1);
            a0 = fmaf(ua.w, w1r.w, a0); a1 = fmaf(ub.w, w1r.w, a1);
            b0 = fmaf(qa.w, wmr.w, b0); b1 = fmaf(qb.w, wmr.w, b1);
        }
        out[(base + ty) * DD + tx]     = 0.5f * (b0 + fmaxf(a0, 0.f));
        out[(base + ty + 4) * DD + tx] = 0.5f * (b1 + fmaxf(a1, 0.f));
        __syncthreads();
    }
}

// ---------------------------------------------------------------------------
// Launch
// ---------------------------------------------------------------------------
extern "C" void kernel_launch(void* const* d_in, const int* in_sizes, int n_in,
                              void* d_out, int out_size) {
    const float* x    = (const float*)d_in[0];
    const void*  ei   = d_in[1];
    const float* W0   = (const float*)d_in[2];
    const float* eps0 = (const float*)d_in[3];
    const float* W1   = (const float*)d_in[4];
    const float* eps1 = (const float*)d_in[5];
    const float* Wm   = (const float*)d_in[6];
    float*       out  = (float*)d_out;

    dim3 gemm_block(64, 4);
    int scatter_blocks = (E_EDGES * 16) / 256;  // 100000 exactly

    detect_dtype_kernel<<<1, 256>>>((const int*)ei);

    // Layer 1
    zero_agg_kernel<<<1184, 256>>>();
    scatter_kernel<<<scatter_blocks, 256>>>(x, ei, 0);
    gin1_kernel<<<1184, gemm_block>>>(x, W0, eps0);

    // Layer 2 + final mix
    zero_agg_kernel<<<1184, 256>>>();
    scatter_kernel<<<scatter_blocks, 256>>>(x, ei, 1);
    final_kernel<<<740, gemm_block>>>(W1, eps1, Wm, out);
}

// round 10
// speedup vs baseline: 2.1906x; 1.3338x over previous
#include <cuda_runtime.h>

#define N_NODES 100000
#define DD 64
#define E_EDGES 1600000
#define SCAN_BLOCKS 98
#define SCAN_CHUNK 1024   // 256 threads * 4 elements

// Scratch (static device globals — no allocation allowed)
__device__ float g_agg[N_NODES * DD];
__device__ float g_h1[N_NODES * DD];
__device__ int   g_row[N_NODES + 1];   // CSR row starts (by dst)
__device__ int   g_cur[N_NODES];       // histogram, then cursors
__device__ int   g_srcp[E_EDGES];      // permuted src indices
__device__ int   g_part[SCAN_BLOCKS];  // scan partials
__device__ int   g_is64;               // edge_index dtype flag

// ---------------------------------------------------------------------------
// Detect edge_index dtype. int64 (values < 2^31) -> all odd int32 words zero.
// ---------------------------------------------------------------------------
__global__ void detect_dtype_kernel(const int* __restrict__ ei32) {
    __shared__ int s_or;
    if (threadIdx.x == 0) s_or = 0;
    __syncthreads();
    int v = 0;
    for (int i = threadIdx.x; i < 4096; i += 256)
        v |= ei32[2 * i + 1];
    atomicOr(&s_or, v);
    __syncthreads();
    if (threadIdx.x == 0) g_is64 = (s_or == 0) ? 1 : 0;
}

// ---------------------------------------------------------------------------
// CSR build: zero counters -> histogram over dst -> 3-step exclusive scan ->
// permute src into dst-sorted order.
// ---------------------------------------------------------------------------
__global__ void zero_cur_kernel() {
    int i = blockIdx.x * blockDim.x + threadIdx.x;
    if (i < N_NODES) g_cur[i] = 0;
}

__global__ void hist_kernel(const void* __restrict__ ei_raw) {
    int e = blockIdx.x * blockDim.x + threadIdx.x;
    if (e >= E_EDGES) return;
    int dst = g_is64 ? (int)((const long long*)ei_raw)[E_EDGES + e]
                     : ((const int*)ei_raw)[E_EDGES + e];
    atomicAdd(&g_cur[dst], 1);
}

__global__ void scan1_kernel() {   // per-block totals
    int b = blockIdx.x, t = threadIdx.x;
    int base = b * SCAN_CHUNK + t * 4;
    int s = 0;
    #pragma unroll
    for (int k = 0; k < 4; k++)
        if (base + k < N_NODES) s += g_cur[base + k];
    __shared__ int sh[256];
    sh[t] = s; __syncthreads();
    for (int d = 128; d > 0; d >>= 1) {
        if (t < d) sh[t] += sh[t + d];
        __syncthreads();
    }
    if (t == 0) g_part[b] = sh[0];
}

__global__ void scan2_kernel() {   // exclusive scan of block totals
    int t = threadIdx.x;
    __shared__ int sh[128];
    int v = (t < SCAN_BLOCKS) ? g_part[t] : 0;
    sh[t] = v; __syncthreads();
    for (int d = 1; d < 128; d <<= 1) {
        int u = (t >= d) ? sh[t - d] : 0;
        __syncthreads();
        sh[t] += u;
        __syncthreads();
    }
    if (t < SCAN_BLOCKS) g_part[t] = sh[t] - v;
}

__global__ void scan3_kernel() {   // write row starts + cursors
    int b = blockIdx.x, t = threadIdx.x;
    int base = b * SCAN_CHUNK + t * 4;
    int c[4]; int lsum = 0;
    #pragma unroll
    for (int k = 0; k < 4; k++) {
        c[k] = (base + k < N_NODES) ? g_cur[base + k] : 0;
        lsum += c[k];
    }
    __shared__ int sh[256];
    sh[t] = lsum; __syncthreads();
    for (int d = 1; d < 256; d <<= 1) {
        int u = (t >= d) ? sh[t - d] : 0;
        __syncthreads();
        sh[t] += u;
        __syncthreads();
    }
    int off = g_part[b] + (sh[t] - lsum);
    #pragma unroll
    for (int k = 0; k < 4; k++) {
        if (base + k < N_NODES) {
            g_row[base + k] = off;
            g_cur[base + k] = off;
            off += c[k];
        }
    }
    if (b == 0 && t == 0) g_row[N_NODES] = E_EDGES;
}

__global__ void permute_kernel(const void* __restrict__ ei_raw) {
    int e = blockIdx.x * blockDim.x + threadIdx.x;
    if (e >= E_EDGES) return;
    int src, dst;
    if (g_is64) {
        const long long* ei = (const long long*)ei_raw;
        src = (int)ei[e];
        dst = (int)ei[E_EDGES + e];
    } else {
        const int* ei = (const int*)ei_raw;
        src = ei[e];
        dst = ei[E_EDGES + e];
    }
    int pos = atomicAdd(&g_cur[dst], 1);
    g_srcp[pos] = src;
}

// ---------------------------------------------------------------------------
// Gather aggregation (atomic-free): one warp per node. Lanes 0-15 / 16-31
// process even/odd edges; each lane owns a float4 chunk of the row.
// Halves combined via shfl.xor 16 at the end.
// ---------------------------------------------------------------------------
__global__ void __launch_bounds__(256) gather_kernel(
        const float* __restrict__ xin, int use_h1) {
    int node = (blockIdx.x * blockDim.x + threadIdx.x) >> 5;
    if (node >= N_NODES) return;
    int lane = threadIdx.x & 31;
    int half = lane >> 4;
    int c = (lane & 15) << 2;

    const float* h = use_h1 ? g_h1 : xin;
    int s = g_row[node], e = g_row[node + 1];

    float4 acc = make_float4(0.f, 0.f, 0.f, 0.f);
    for (int j = s + half; j < e; j += 2) {
        int src = __ldg(&g_srcp[j]);
        float4 v = *reinterpret_cast<const float4*>(h + src * DD + c);
        acc.x += v.x; acc.y += v.y; acc.z += v.z; acc.w += v.w;
    }
    const unsigned m = 0xffffffffu;
    acc.x += __shfl_xor_sync(m, acc.x, 16);
    acc.y += __shfl_xor_sync(m, acc.y, 16);
    acc.z += __shfl_xor_sync(m, acc.z, 16);
    acc.w += __shfl_xor_sync(m, acc.w, 16);
    if (half == 0)
        *reinterpret_cast<float4*>(g_agg + node * DD + c) = acc;
}

// ---------------------------------------------------------------------------
// GEMM kernels: thread owns output column tx; its W row lives in 16 float4
// REGISTERS for the whole kernel. Activations are staged in smem and read as
// warp-uniform broadcasts (conflict-free). blockDim (64,4), 8 nodes/tile.
// ---------------------------------------------------------------------------
// Layer 1: g_h1 = relu((g_agg + (1+eps0)*x) @ W0^T)
__global__ void __launch_bounds__(256) gin1_kernel(
        const float* __restrict__ x,
        const float* __restrict__ W0,
        const float* __restrict__ eps0p) {
    int tx = threadIdx.x, ty = threadIdx.y;

    float4 wr[16];
    const float4* wg = reinterpret_cast<const float4*>(W0 + tx * DD);
    #pragma unroll
    for (int i = 0; i < 16; i++) wr[i] = wg[i];
    float se = 1.0f + *eps0p;

    __shared__ float hs[8][64];

    int ntiles = N_NODES / 8;
    for (int tile = blockIdx.x; tile < ntiles; tile += gridDim.x) {
        int base = tile * 8;
        #pragma unroll
        for (int r = 0; r < 2; r++) {
            int node = base + ty + r * 4;
            hs[ty + r * 4][tx] = g_agg[node * DD + tx] + se * x[node * DD + tx];
        }
        __syncthreads();

        const float4* h0 = reinterpret_cast<const float4*>(&hs[ty][0]);
        const float4* h1 = reinterpret_cast<const float4*>(&hs[ty + 4][0]);
        float acc0 = 0.f, acc1 = 0.f;
        #pragma unroll
        for (int kk = 0; kk < 16; kk++) {
            float4 w = wr[kk];
            float4 a = h0[kk];
            float4 b = h1[kk];
            acc0 = fmaf(a.x, w.x, acc0); acc1 = fmaf(b.x, w.x, acc1);
            acc0 = fmaf(a.y, w.y, acc0); acc1 = fmaf(b.y, w.y, acc1);
            acc0 = fmaf(a.z, w.z, acc0); acc1 = fmaf(b.z, w.z, acc1);
            acc0 = fmaf(a.w, w.w, acc0); acc1 = fmaf(b.w, w.w, acc1);
        }
        g_h1[(base + ty) * DD + tx]     = fmaxf(acc0, 0.f);
        g_h1[(base + ty + 4) * DD + tx] = fmaxf(acc1, 0.f);
        __syncthreads();
    }
}

// F1: g_agg = relu((g_agg + (1+eps1)*g_h1) @ W1^T)   (in-place, row-local)
__global__ void __launch_bounds__(256) f1_kernel(
        const float* __restrict__ W1,
        const float* __restrict__ eps1p) {
    int tx = threadIdx.x, ty = threadIdx.y;

    float4 wr[16];
    const float4* wg = reinterpret_cast<const float4*>(W1 + tx * DD);
    #pragma unroll
    for (int i = 0; i < 16; i++) wr[i] = wg[i];
    float se = 1.0f + *eps1p;

    __shared__ float us[8][64];

    int ntiles = N_NODES / 8;
    for (int tile = blockIdx.x; tile < ntiles; tile += gridDim.x) {
        int base = tile * 8;
        #pragma unroll
        for (int r = 0; r < 2; r++) {
            int node = base + ty + r * 4;
            us[ty + r * 4][tx] = g_agg[node * DD + tx] + se * g_h1[node * DD + tx];
        }
        __syncthreads();

        const float4* u0 = reinterpret_cast<const float4*>(&us[ty][0]);
        const float4* u1 = reinterpret_cast<const float4*>(&us[ty + 4][0]);
        float acc0 = 0.f, acc1 = 0.f;
        #pragma unroll
        for (int kk = 0; kk < 16; kk++) {
            float4 w = wr[kk];
            float4 a = u0[kk];
            float4 b = u1[kk];
            acc0 = fmaf(a.x, w.x, acc0); acc1 = fmaf(b.x, w.x, acc1);
            acc0 = fmaf(a.y, w.y, acc0); acc1 = fmaf(b.y, w.y, acc1);
            acc0 = fmaf(a.z, w.z, acc0); acc1 = fmaf(b.z, w.z, acc1);
            acc0 = fmaf(a.w, w.w, acc0); acc1 = fmaf(b.w, w.w, acc1);
        }
        g_agg[(base + ty) * DD + tx]     = fmaxf(acc0, 0.f);
        g_agg[(base + ty + 4) * DD + tx] = fmaxf(acc1, 0.f);
        __syncthreads();
    }
}

// F2: out = 0.5 * (g_h1 @ Wm^T + g_agg)
__global__ void __launch_bounds__(256) f2_kernel(
        const float* __restrict__ Wm,
        float* __restrict__ out) {
    int tx = threadIdx.x, ty = threadIdx.y;

    float4 wr[16];
    const float4* wg = reinterpret_cast<const float4*>(Wm + tx * DD);
    #pragma unroll
    for (int i = 0; i < 16; i++) wr[i] = wg[i];

    __shared__ float hh[8][64];

    int ntiles = N_NODES / 8;
    for (int tile = blockIdx.x; tile < ntiles; tile += gridDim.x) {
        int base = tile * 8;
        #pragma unroll
        for (int r = 0; r < 2; r++) {
            int node = base + ty + r * 4;
            hh[ty + r * 4][tx] = g_h1[node * DD + tx];
        }
        __syncthreads();

        const float4* h0 = reinterpret_cast<const float4*>(&hh[ty][0]);
        const float4* h1 = reinterpret_cast<const float4*>(&hh[ty + 4][0]);
        float acc0 = 0.f, acc1 = 0.f;
        #pragma unroll
        for (int kk = 0; kk < 16; kk++) {
            float4 w = wr[kk];
            float4 a = h0[kk];
            float4 b = h1[kk];
            acc0 = fmaf(a.x, w.x, acc0); acc1 = fmaf(b.x, w.x, acc1);
            acc0 = fmaf(a.y, w.y, acc0); acc1 = fmaf(b.y, w.y, acc1);
            acc0 = fmaf(a.z, w.z, acc0); acc1 = fmaf(b.z, w.z, acc1);
            acc0 = fmaf(a.w, w.w, acc0); acc1 = fmaf(b.w, w.w, acc1);
        }
        int n0 = (base + ty) * DD + tx;
        int n1 = (base + ty + 4) * DD + tx;
        out[n0] = 0.5f * (acc0 + g_agg[n0]);
        out[n1] = 0.5f * (acc1 + g_agg[n1]);
        __syncthreads();
    }
}

// ---------------------------------------------------------------------------
// Launch
// ---------------------------------------------------------------------------
extern "C" void kernel_launch(void* const* d_in, const int* in_sizes, int n_in,
                              void* d_out, int out_size) {
    const float* x    = (const float*)d_in[0];
    const void*  ei   = d_in[1];
    const float* W0   = (const float*)d_in[2];
    const float* eps0 = (const float*)d_in[3];
    const float* W1   = (const float*)d_in[4];
    const float* eps1 = (const float*)d_in[5];
    const float* Wm   = (const float*)d_in[6];
    float*       out  = (float*)d_out;

    dim3 gemm_block(64, 4);

    detect_dtype_kernel<<<1, 256>>>((const int*)ei);

    // CSR build (once; reused by both layers)
    zero_cur_kernel<<<(N_NODES + 255) / 256, 256>>>();
    hist_kernel<<<E_EDGES / 256, 256>>>(ei);
    scan1_kernel<<<SCAN_BLOCKS, 256>>>();
    scan2_kernel<<<1, 128>>>();
    scan3_kernel<<<SCAN_BLOCKS, 256>>>();
    permute_kernel<<<E_EDGES / 256, 256>>>(ei);

    // Layer 1
    gather_kernel<<<(N_NODES * 32) / 256, 256>>>(x, 0);
    gin1_kernel<<<1184, gemm_block>>>(x, W0, eps0);

    // Layer 2 + final mix
    gather_kernel<<<(N_NODES * 32) / 256, 256>>>(x, 1);
    f1_kernel<<<1184, gemm_block>>>(W1, eps1);
    f2_kernel<<<1184, gemm_block>>>(Wm, out);
}